// round 5
// baseline (speedup 1.0000x reference)
#include <cuda_runtime.h>
#include <cuda_bf16.h>

// NeighborIntegration: B=64, K=64, D=128
//
// y[b,i] = 0.5*( V[b,i] @ W1a + scale[b,i] * (stu[b] @ W1b + b1) )
//   V     = 64*mask_c*concept[b,i] + sum_j mask_n(b,i,j)*neigh[b,i,j]
//   scale = 64*mask_c + cnt_n
//
// Kernel R: pure streaming masked reduction -> V, scale scratch (no W1).
// Kernel G: tiled GEMM V@W1a + epilogue; a2 computed per block (per-b).

#define D_ 128
#define K_ 64
#define NBI 4096

__device__ float g_V[NBI * D_];     // 2 MB scratch (L2-resident)
__device__ float g_scale[NBI];

__device__ __forceinline__ float warp_sum(float x) {
#pragma unroll
    for (int o = 16; o > 0; o >>= 1)
        x += __shfl_xor_sync(0xffffffffu, x, o);
    return x;
}

// ---------------------------------------------------------------------------
// Kernel R: one block per (b,i). 8 warps x 8 rows masked streaming reduction.
// ---------------------------------------------------------------------------
__global__ __launch_bounds__(256)
void reduce_kernel(const float* __restrict__ concept_,  // [64,64,128]
                   const float* __restrict__ neigh)     // [64,64,64,128]
{
    const int bi   = blockIdx.x;
    const int tid  = threadIdx.x;
    const int w    = tid >> 5;
    const int lane = tid & 31;

    __shared__ float s_acc[8][D_];
    __shared__ float s_cnt[8];
    __shared__ float s_red[4];

    const float4* nbase = reinterpret_cast<const float4*>(neigh) +
                          (size_t)bi * (K_ * 32);
    float4 r[8];
#pragma unroll
    for (int u = 0; u < 8; ++u)
        r[u] = __ldcs(&nbase[(w * 8 + u) * 32 + lane]);   // MLP=8/warp

    float4 acc = make_float4(0.f, 0.f, 0.f, 0.f);
    float  cnt = 0.f;
#pragma unroll
    for (int u = 0; u < 8; ++u) {
        const float rs = warp_sum((r[u].x + r[u].y) + (r[u].z + r[u].w));
        if (rs != 0.0f) {               // mask_n (warp-uniform)
            acc.x += r[u].x; acc.y += r[u].y;
            acc.z += r[u].z; acc.w += r[u].w;
            cnt   += 1.0f;
        }
    }
    reinterpret_cast<float4*>(s_acc[w])[lane] = acc;
    if (lane == 0) s_cnt[w] = cnt;
    __syncthreads();

    float R = 0.f, c = 0.f;
    if (tid < D_) {
#pragma unroll
        for (int ww = 0; ww < 8; ++ww) R += s_acc[ww][tid];
        c = concept_[(size_t)bi * D_ + tid];
    }
    const float cs = warp_sum(c);       // warps 0..3 carry concept
    if (lane == 0 && w < 4) s_red[w] = cs;
    __syncthreads();

    const float csum = s_red[0] + s_red[1] + s_red[2] + s_red[3];
    const float mc   = (csum != 0.0f) ? 64.0f : 0.0f;

    if (tid < D_)
        g_V[(size_t)bi * D_ + tid] = fmaf(mc, c, R);
    if (tid == 128) {
        const float cntn = s_cnt[0] + s_cnt[1] + s_cnt[2] + s_cnt[3] +
                           s_cnt[4] + s_cnt[5] + s_cnt[6] + s_cnt[7];
        g_scale[bi] = mc + cntn;
    }
}

// ---------------------------------------------------------------------------
// Kernel G: block = (b, 32-row i-tile). out = V@W1a + scale*(stu@W1b+b1), *0.5
// ---------------------------------------------------------------------------
__global__ __launch_bounds__(256)
void gemm_kernel(const float* __restrict__ stu,   // [64,128]
                 const float* __restrict__ W1,    // [256,128]
                 const float* __restrict__ b1,    // [128]
                 float* __restrict__ out)         // [64,64,128]
{
    const int b   = blockIdx.x >> 1;
    const int i0  = (blockIdx.x & 1) << 5;        // 0 or 32
    const int tid = threadIdx.x;

    __shared__ float s_stu[D_];
    __shared__ float s_p[256];
    __shared__ float s_a2[D_];
    __shared__ float s_scale[32];
    __shared__ float s_v[32][D_];                 // 16 KB V tile

    // a2 = stu[b] @ W1b + b1 (256 threads: d x 2 k-halves)
    if (tid < D_) s_stu[tid] = stu[b * D_ + tid];
    __syncthreads();
    {
        const int d  = tid & 127;
        const int kb = (tid >> 7) * 64;
        float p = 0.f;
#pragma unroll 8
        for (int kk = 0; kk < 64; ++kk)
            p = fmaf(s_stu[kb + kk], W1[(size_t)(D_ + kb + kk) * D_ + d], p);
        s_p[tid] = p;
    }
    // V tile + scales (independent of s_p; no sync needed yet)
    {
        const int base = ((size_t)0, (b * 64 + i0) * (D_ / 4));
        const float4* Vg = reinterpret_cast<const float4*>(g_V) + base;
        float4* Vs = reinterpret_cast<float4*>(s_v);
#pragma unroll
        for (int u = 0; u < 4; ++u)
            Vs[u * 256 + tid] = Vg[u * 256 + tid];
        if (tid < 32) s_scale[tid] = g_scale[b * 64 + i0 + tid];
    }
    __syncthreads();
    if (tid < D_) s_a2[tid] = s_p[tid] + s_p[tid + 128] + b1[tid];
    __syncthreads();

    // GEMM: thread owns d-quad (d4 = tid&31) and 4 rows (rg = tid>>5).
    const int d4 = tid & 31;
    const int r0 = (tid >> 5) * 4;                // local rows r0..r0+3
    float4 a0 = make_float4(0.f,0.f,0.f,0.f);
    float4 a1 = a0, a2r = a0, a3 = a0;

    const float4* Wq = reinterpret_cast<const float4*>(W1) + d4;
#pragma unroll 4
    for (int k = 0; k < D_; ++k) {
        const float4 wv = Wq[k * 32];             // W1a[k][4*d4..], L1-hot
        const float v0 = s_v[r0 + 0][k];
        const float v1 = s_v[r0 + 1][k];
        const float v2 = s_v[r0 + 2][k];
        const float v3 = s_v[r0 + 3][k];
        a0.x = fmaf(v0, wv.x, a0.x); a0.y = fmaf(v0, wv.y, a0.y);
        a0.z = fmaf(v0, wv.z, a0.z); a0.w = fmaf(v0, wv.w, a0.w);
        a1.x = fmaf(v1, wv.x, a1.x); a1.y = fmaf(v1, wv.y, a1.y);
        a1.z = fmaf(v1, wv.z, a1.z); a1.w = fmaf(v1, wv.w, a1.w);
        a2r.x = fmaf(v2, wv.x, a2r.x); a2r.y = fmaf(v2, wv.y, a2r.y);
        a2r.z = fmaf(v2, wv.z, a2r.z); a2r.w = fmaf(v2, wv.w, a2r.w);
        a3.x = fmaf(v3, wv.x, a3.x); a3.y = fmaf(v3, wv.y, a3.y);
        a3.z = fmaf(v3, wv.z, a3.z); a3.w = fmaf(v3, wv.w, a3.w);
    }

    const float4 a2q = reinterpret_cast<const float4*>(s_a2)[d4];
    float4* og = reinterpret_cast<float4*>(out) +
                 (size_t)(b * 64 + i0 + r0) * 32 + d4;
    float4 res;
    float sc;
    sc = s_scale[r0 + 0];
    res.x = 0.5f * fmaf(sc, a2q.x, a0.x); res.y = 0.5f * fmaf(sc, a2q.y, a0.y);
    res.z = 0.5f * fmaf(sc, a2q.z, a0.z); res.w = 0.5f * fmaf(sc, a2q.w, a0.w);
    og[0] = res;
    sc = s_scale[r0 + 1];
    res.x = 0.5f * fmaf(sc, a2q.x, a1.x); res.y = 0.5f * fmaf(sc, a2q.y, a1.y);
    res.z = 0.5f * fmaf(sc, a2q.z, a1.z); res.w = 0.5f * fmaf(sc, a2q.w, a1.w);
    og[32] = res;
    sc = s_scale[r0 + 2];
    res.x = 0.5f * fmaf(sc, a2q.x, a2r.x); res.y = 0.5f * fmaf(sc, a2q.y, a2r.y);
    res.z = 0.5f * fmaf(sc, a2q.z, a2r.z); res.w = 0.5f * fmaf(sc, a2q.w, a2r.w);
    og[64] = res;
    sc = s_scale[r0 + 3];
    res.x = 0.5f * fmaf(sc, a2q.x, a3.x); res.y = 0.5f * fmaf(sc, a2q.y, a3.y);
    res.z = 0.5f * fmaf(sc, a2q.z, a3.z); res.w = 0.5f * fmaf(sc, a2q.w, a3.w);
    og[96] = res;
}

extern "C" void kernel_launch(void* const* d_in, const int* in_sizes, int n_in,
                              void* d_out, int out_size)
{
    const float* stu      = (const float*)d_in[0];
    const float* concept_ = (const float*)d_in[1];
    const float* neigh    = (const float*)d_in[2];
    const float* W1       = (const float*)d_in[3];
    const float* b1       = (const float*)d_in[4];
    // d_in[5]=Wn, d_in[6]=bn: dead (softmax over size-1 axis == 1)
    float* out = (float*)d_out;

    reduce_kernel<<<NBI, 256>>>(concept_, neigh);
    gemm_kernel<<<128, 256>>>(stu, W1, b1, out);
}

// round 6
// speedup vs baseline: 1.1527x; 1.1527x over previous
#include <cuda_runtime.h>
#include <cuda_bf16.h>

// NeighborIntegration: B=64, K=64, D=128
//
// y[b,i] = 0.5*( v@W1a + scale*(stu@W1b + b1) )
//        = 0.5*( v'@W1 + scale*b1 ),  v' = [v, scale*stu]  (256-long)
//   v     = 64*mask_c*concept[b,i] + sum_j mask_n(b,i,j)*neigh[b,i,j]
//   scale = 64*mask_c + cnt_n
//
// One kernel, grid=1024: block = (b, 4 consecutive i).
//   Phase 1: 8 warps (2 per i) x 32 rows masked streaming reduction, MLP=8.
//   Phase 2: build packed v' transpose: s_vT[k] = float4 over the 4 i's.
//   Phase 3: 4x128x256 mini-GEMM: per k, 1 LDS.128 + 1 LDG.128 + 16 FMA.
//   Phase 4: 8-way partial reduce + scale*b1 epilogue.

#define D_ 128
#define K_ 64

__device__ __forceinline__ float warp_sum(float x) {
#pragma unroll
    for (int o = 16; o > 0; o >>= 1)
        x += __shfl_xor_sync(0xffffffffu, x, o);
    return x;
}

__global__ __launch_bounds__(256)
void neighbor_integration_kernel(const float* __restrict__ stu,       // [64,128]
                                 const float* __restrict__ concept_,  // [64,64,128]
                                 const float* __restrict__ neigh,     // [64,64,64,128]
                                 const float* __restrict__ W1,        // [256,128]
                                 const float* __restrict__ b1,        // [128]
                                 float* __restrict__ out)             // [64,64,128]
{
    const int blk  = blockIdx.x;          // 1024
    const int b    = blk >> 4;
    const int i0   = (blk & 15) << 2;     // 4 i's per block
    const int bi0  = b * 64 + i0;
    const int tid  = threadIdx.x;
    const int w    = tid >> 5;            // warp 0..7
    const int lane = tid & 31;

    __shared__ float  s_acc[8][D_];       // per-warp masked accumulators
    __shared__ float  s_cnt[8];
    __shared__ float4 s_cc[4][32];        // concept rows
    __shared__ float  s_mc[4];            // 64*mask_c per i
    __shared__ float  s_scale[4];
    __shared__ float4 s_stu4[32];
    __shared__ float4 s_vT[256];          // v'[k] packed across 4 i (4 KB)
    __shared__ float4 s_part[8][4][32];   // GEMM partials (16 KB)

    if (tid < 32)
        s_stu4[tid] = reinterpret_cast<const float4*>(stu + (size_t)b * D_)[tid];

    // ---------------- Phase 1: masked reduction (2 warps per i) -----------
    const int il = w >> 1;                         // local i 0..3
    const int jh = (w & 1) << 5;                   // j half: 0 or 32
    const float4* nbase = reinterpret_cast<const float4*>(neigh) +
                          ((size_t)(bi0 + il) * K_ + jh) * 32;
    float4 acc = make_float4(0.f, 0.f, 0.f, 0.f);
    float  cnt = 0.f;
    for (int jb = 0; jb < 32; jb += 8) {
        float4 r[8];
#pragma unroll
        for (int u = 0; u < 8; ++u)
            r[u] = __ldcs(&nbase[(jb + u) * 32 + lane]);   // MLP=8/warp
#pragma unroll
        for (int u = 0; u < 8; ++u) {
            const float rs = warp_sum((r[u].x + r[u].y) + (r[u].z + r[u].w));
            if (rs != 0.0f) {                              // warp-uniform
                acc.x += r[u].x; acc.y += r[u].y;
                acc.z += r[u].z; acc.w += r[u].w;
                cnt   += 1.0f;
            }
        }
    }
    reinterpret_cast<float4*>(s_acc[w])[lane] = acc;
    if (lane == 0) s_cnt[w] = cnt;

    // concept rows + masks: warps 0..3, one i each
    if (w < 4) {
        const float4 cc = reinterpret_cast<const float4*>(concept_)
                              [(size_t)(bi0 + w) * 32 + lane];
        const float cs = warp_sum((cc.x + cc.y) + (cc.z + cc.w));
        s_cc[w][lane] = cc;
        if (lane == 0) s_mc[w] = (cs != 0.0f) ? 64.0f : 0.0f;
    }
    __syncthreads();

    // ---------------- Phase 2: build packed v' transpose -------------------
    if (tid < 4) s_scale[tid] = s_mc[tid] + s_cnt[2 * tid] + s_cnt[2 * tid + 1];
    {
        const float* s_stu = reinterpret_cast<const float*>(s_stu4);
        const float* s_ccf = reinterpret_cast<const float*>(s_cc);
        float* vT = reinterpret_cast<float*>(s_vT);
#pragma unroll
        for (int pass = 0; pass < 2; ++pass) {
            const int idx = pass * 256 + tid;     // 0..511
            const int i   = idx >> 7;
            const int d   = idx & 127;
            const float mc = s_mc[i];
            const float sc = mc + s_cnt[2 * i] + s_cnt[2 * i + 1];
            const float R  = s_acc[2 * i][d] + s_acc[2 * i + 1][d];
            vT[d * 4 + i]         = fmaf(mc, s_ccf[i * 128 + d], R);  // v
            vT[(128 + d) * 4 + i] = sc * s_stu[d];                    // scale*stu
        }
    }
    __syncthreads();

    // ---------------- Phase 3: 4x128x256 mini-GEMM ------------------------
    // Warp w: k in [32w, 32w+32). Lane owns d-quad d4=lane.
    float4 a0 = make_float4(0.f,0.f,0.f,0.f);
    float4 a1 = a0, a2 = a0, a3 = a0;
    {
        const int kb = w * 32;
        const float4* Wq = reinterpret_cast<const float4*>(W1) + lane;
#pragma unroll 8
        for (int kk = 0; kk < 32; ++kk) {
            const int k = kb + kk;
            const float4 wv = Wq[k * 32];       // W1[k][4*lane..], L1-hot
            const float4 vv = s_vT[k];          // one LDS.128 broadcast
            a0.x = fmaf(vv.x, wv.x, a0.x); a0.y = fmaf(vv.x, wv.y, a0.y);
            a0.z = fmaf(vv.x, wv.z, a0.z); a0.w = fmaf(vv.x, wv.w, a0.w);
            a1.x = fmaf(vv.y, wv.x, a1.x); a1.y = fmaf(vv.y, wv.y, a1.y);
            a1.z = fmaf(vv.y, wv.z, a1.z); a1.w = fmaf(vv.y, wv.w, a1.w);
            a2.x = fmaf(vv.z, wv.x, a2.x); a2.y = fmaf(vv.z, wv.y, a2.y);
            a2.z = fmaf(vv.z, wv.z, a2.z); a2.w = fmaf(vv.z, wv.w, a2.w);
            a3.x = fmaf(vv.w, wv.x, a3.x); a3.y = fmaf(vv.w, wv.y, a3.y);
            a3.z = fmaf(vv.w, wv.z, a3.z); a3.w = fmaf(vv.w, wv.w, a3.w);
        }
    }
    s_part[w][0][lane] = a0;
    s_part[w][1][lane] = a1;
    s_part[w][2][lane] = a2;
    s_part[w][3][lane] = a3;
    __syncthreads();

    // ---------------- Phase 4: reduce partials + epilogue ------------------
    {
        const float* sp = reinterpret_cast<const float*>(s_part); // [8][4][128]
#pragma unroll
        for (int pass = 0; pass < 2; ++pass) {
            const int idx = pass * 256 + tid;
            const int i   = idx >> 7;
            const int d   = idx & 127;
            float o = 0.f;
#pragma unroll
            for (int ww = 0; ww < 8; ++ww)
                o += sp[(ww * 4 + i) * 128 + d];
            out[(size_t)(bi0 + i) * D_ + d] = 0.5f * fmaf(s_scale[i], b1[d], o);
        }
    }
}

extern "C" void kernel_launch(void* const* d_in, const int* in_sizes, int n_in,
                              void* d_out, int out_size)
{
    const float* stu      = (const float*)d_in[0];
    const float* concept_ = (const float*)d_in[1];
    const float* neigh    = (const float*)d_in[2];
    const float* W1       = (const float*)d_in[3];
    const float* b1       = (const float*)d_in[4];
    // d_in[5]=Wn, d_in[6]=bn: dead (softmax over size-1 axis == 1)
    float* out = (float*)d_out;

    neighbor_integration_kernel<<<1024, 256>>>(stu, concept_, neigh, W1, b1, out);
}

// round 7
// speedup vs baseline: 1.1536x; 1.0009x over previous
#include <cuda_runtime.h>
#include <cuda_bf16.h>

// NeighborIntegration: B=64, K=64, D=128
//
// y[b,i] = 0.5*( v@W1a + scale*(stu@W1b + b1) )
//        = 0.5*( v'@W1 + scale*b1 ),  v' = [v, scale*stu]  (256-long)
//   v     = 64*mask_c*concept[b,i] + sum_j mask_n(b,i,j)*neigh[b,i,j]
//   scale = 64*mask_c + cnt_n
//
// One kernel, grid=1024: block = (b, 4 consecutive i).
//   Phase 1: 8 warps (2 per i) x 32 rows masked streaming reduction, MLP=8.
//   Phase 2: build packed v' transpose: s_vT[k] = float4 over the 4 i's.
//   Phase 3: 4x128x256 mini-GEMM: per k, 1 LDS.128 + 1 LDG.128 + 16 FMA.
//   Phase 4: 8-way partial reduce + scale*b1 epilogue.

#define D_ 128
#define K_ 64

__device__ __forceinline__ float warp_sum(float x) {
#pragma unroll
    for (int o = 16; o > 0; o >>= 1)
        x += __shfl_xor_sync(0xffffffffu, x, o);
    return x;
}

__global__ __launch_bounds__(256)
void neighbor_integration_kernel(const float* __restrict__ stu,       // [64,128]
                                 const float* __restrict__ concept_,  // [64,64,128]
                                 const float* __restrict__ neigh,     // [64,64,64,128]
                                 const float* __restrict__ W1,        // [256,128]
                                 const float* __restrict__ b1,        // [128]
                                 float* __restrict__ out)             // [64,64,128]
{
    const int blk  = blockIdx.x;          // 1024
    const int b    = blk >> 4;
    const int i0   = (blk & 15) << 2;     // 4 i's per block
    const int bi0  = b * 64 + i0;
    const int tid  = threadIdx.x;
    const int w    = tid >> 5;            // warp 0..7
    const int lane = tid & 31;

    __shared__ float  s_acc[8][D_];       // per-warp masked accumulators
    __shared__ float  s_cnt[8];
    __shared__ float4 s_cc[4][32];        // concept rows
    __shared__ float  s_mc[4];            // 64*mask_c per i
    __shared__ float  s_scale[4];
    __shared__ float4 s_stu4[32];
    __shared__ float4 s_vT[256];          // v'[k] packed across 4 i (4 KB)
    __shared__ float4 s_part[8][4][32];   // GEMM partials (16 KB)

    if (tid < 32)
        s_stu4[tid] = reinterpret_cast<const float4*>(stu + (size_t)b * D_)[tid];

    // ---------------- Phase 1: masked reduction (2 warps per i) -----------
    const int il = w >> 1;                         // local i 0..3
    const int jh = (w & 1) << 5;                   // j half: 0 or 32
    const float4* nbase = reinterpret_cast<const float4*>(neigh) +
                          ((size_t)(bi0 + il) * K_ + jh) * 32;
    float4 acc = make_float4(0.f, 0.f, 0.f, 0.f);
    float  cnt = 0.f;
    for (int jb = 0; jb < 32; jb += 8) {
        float4 r[8];
#pragma unroll
        for (int u = 0; u < 8; ++u)
            r[u] = __ldcs(&nbase[(jb + u) * 32 + lane]);   // MLP=8/warp
#pragma unroll
        for (int u = 0; u < 8; ++u) {
            const float rs = warp_sum((r[u].x + r[u].y) + (r[u].z + r[u].w));
            if (rs != 0.0f) {                              // warp-uniform
                acc.x += r[u].x; acc.y += r[u].y;
                acc.z += r[u].z; acc.w += r[u].w;
                cnt   += 1.0f;
            }
        }
    }
    reinterpret_cast<float4*>(s_acc[w])[lane] = acc;
    if (lane == 0) s_cnt[w] = cnt;

    // concept rows + masks: warps 0..3, one i each
    if (w < 4) {
        const float4 cc = reinterpret_cast<const float4*>(concept_)
                              [(size_t)(bi0 + w) * 32 + lane];
        const float cs = warp_sum((cc.x + cc.y) + (cc.z + cc.w));
        s_cc[w][lane] = cc;
        if (lane == 0) s_mc[w] = (cs != 0.0f) ? 64.0f : 0.0f;
    }
    __syncthreads();

    // ---------------- Phase 2: build packed v' transpose -------------------
    if (tid < 4) s_scale[tid] = s_mc[tid] + s_cnt[2 * tid] + s_cnt[2 * tid + 1];
    {
        const float* s_stu = reinterpret_cast<const float*>(s_stu4);
        const float* s_ccf = reinterpret_cast<const float*>(s_cc);
        float* vT = reinterpret_cast<float*>(s_vT);
#pragma unroll
        for (int pass = 0; pass < 2; ++pass) {
            const int idx = pass * 256 + tid;     // 0..511
            const int i   = idx >> 7;
            const int d   = idx & 127;
            const float mc = s_mc[i];
            const float sc = mc + s_cnt[2 * i] + s_cnt[2 * i + 1];
            const float R  = s_acc[2 * i][d] + s_acc[2 * i + 1][d];
            vT[d * 4 + i]         = fmaf(mc, s_ccf[i * 128 + d], R);  // v
            vT[(128 + d) * 4 + i] = sc * s_stu[d];                    // scale*stu
        }
    }
    __syncthreads();

    // ---------------- Phase 3: 4x128x256 mini-GEMM ------------------------
    // Warp w: k in [32w, 32w+32). Lane owns d-quad d4=lane.
    float4 a0 = make_float4(0.f,0.f,0.f,0.f);
    float4 a1 = a0, a2 = a0, a3 = a0;
    {
        const int kb = w * 32;
        const float4* Wq = reinterpret_cast<const float4*>(W1) + lane;
#pragma unroll 8
        for (int kk = 0; kk < 32; ++kk) {
            const int k = kb + kk;
            const float4 wv = Wq[k * 32];       // W1[k][4*lane..], L1-hot
            const float4 vv = s_vT[k];          // one LDS.128 broadcast
            a0.x = fmaf(vv.x, wv.x, a0.x); a0.y = fmaf(vv.x, wv.y, a0.y);
            a0.z = fmaf(vv.x, wv.z, a0.z); a0.w = fmaf(vv.x, wv.w, a0.w);
            a1.x = fmaf(vv.y, wv.x, a1.x); a1.y = fmaf(vv.y, wv.y, a1.y);
            a1.z = fmaf(vv.y, wv.z, a1.z); a1.w = fmaf(vv.y, wv.w, a1.w);
            a2.x = fmaf(vv.z, wv.x, a2.x); a2.y = fmaf(vv.z, wv.y, a2.y);
            a2.z = fmaf(vv.z, wv.z, a2.z); a2.w = fmaf(vv.z, wv.w, a2.w);
            a3.x = fmaf(vv.w, wv.x, a3.x); a3.y = fmaf(vv.w, wv.y, a3.y);
            a3.z = fmaf(vv.w, wv.z, a3.z); a3.w = fmaf(vv.w, wv.w, a3.w);
        }
    }
    s_part[w][0][lane] = a0;
    s_part[w][1][lane] = a1;
    s_part[w][2][lane] = a2;
    s_part[w][3][lane] = a3;
    __syncthreads();

    // ---------------- Phase 4: reduce partials + epilogue ------------------
    {
        const float* sp = reinterpret_cast<const float*>(s_part); // [8][4][128]
#pragma unroll
        for (int pass = 0; pass < 2; ++pass) {
            const int idx = pass * 256 + tid;
            const int i   = idx >> 7;
            const int d   = idx & 127;
            float o = 0.f;
#pragma unroll
            for (int ww = 0; ww < 8; ++ww)
                o += sp[(ww * 4 + i) * 128 + d];
            out[(size_t)(bi0 + i) * D_ + d] = 0.5f * fmaf(s_scale[i], b1[d], o);
        }
    }
}

extern "C" void kernel_launch(void* const* d_in, const int* in_sizes, int n_in,
                              void* d_out, int out_size)
{
    const float* stu      = (const float*)d_in[0];
    const float* concept_ = (const float*)d_in[1];
    const float* neigh    = (const float*)d_in[2];
    const float* W1       = (const float*)d_in[3];
    const float* b1       = (const float*)d_in[4];
    // d_in[5]=Wn, d_in[6]=bn: dead (softmax over size-1 axis == 1)
    float* out = (float*)d_out;

    neighbor_integration_kernel<<<1024, 256>>>(stu, concept_, neigh, W1, b1, out);
}

// round 8
// speedup vs baseline: 1.1606x; 1.0060x over previous
#include <cuda_runtime.h>
#include <cuda_bf16.h>

// NeighborIntegration: B=64, K=64, D=128
//
// y[b,i] = 0.5*( v@W1a + scale*(stu@W1b + b1) )
//        = 0.5*( v'@W1 + scale*b1 ),  v' = [v, scale*stu]  (256-long)
//   v     = 64*mask_c*concept[b,i] + sum_j mask_n(b,i,j)*neigh[b,i,j]
//   scale = 64*mask_c + cnt_n
//
// One kernel, grid=1024: block = (b, 4 consecutive i).
//   Phase 1: 8 warps (2 per i) x 32 rows masked streaming reduction, MLP=8.
//   Phase 2: build packed v' transpose: s_vT[k] = float4 over the 4 i's.
//   Phase 3: 4x128x256 mini-GEMM: per k, 1 LDS.128 + 1 LDG.128 + 16 FMA.
//   Phase 4: 8-way partial reduce + scale*b1 epilogue.

#define D_ 128
#define K_ 64

__device__ __forceinline__ float warp_sum(float x) {
#pragma unroll
    for (int o = 16; o > 0; o >>= 1)
        x += __shfl_xor_sync(0xffffffffu, x, o);
    return x;
}

__global__ __launch_bounds__(256)
void neighbor_integration_kernel(const float* __restrict__ stu,       // [64,128]
                                 const float* __restrict__ concept_,  // [64,64,128]
                                 const float* __restrict__ neigh,     // [64,64,64,128]
                                 const float* __restrict__ W1,        // [256,128]
                                 const float* __restrict__ b1,        // [128]
                                 float* __restrict__ out)             // [64,64,128]
{
    const int blk  = blockIdx.x;          // 1024
    const int b    = blk >> 4;
    const int i0   = (blk & 15) << 2;     // 4 i's per block
    const int bi0  = b * 64 + i0;
    const int tid  = threadIdx.x;
    const int w    = tid >> 5;            // warp 0..7
    const int lane = tid & 31;

    __shared__ float  s_acc[8][D_];       // per-warp masked accumulators
    __shared__ float  s_cnt[8];
    __shared__ float4 s_cc[4][32];        // concept rows
    __shared__ float  s_mc[4];            // 64*mask_c per i
    __shared__ float  s_scale[4];
    __shared__ float4 s_stu4[32];
    __shared__ float4 s_vT[256];          // v'[k] packed across 4 i (4 KB)
    __shared__ float4 s_part[8][4][32];   // GEMM partials (16 KB)

    if (tid < 32)
        s_stu4[tid] = reinterpret_cast<const float4*>(stu + (size_t)b * D_)[tid];

    // ---------------- Phase 1: masked reduction (2 warps per i) -----------
    const int il = w >> 1;                         // local i 0..3
    const int jh = (w & 1) << 5;                   // j half: 0 or 32
    const float4* nbase = reinterpret_cast<const float4*>(neigh) +
                          ((size_t)(bi0 + il) * K_ + jh) * 32;
    float4 acc = make_float4(0.f, 0.f, 0.f, 0.f);
    float  cnt = 0.f;
    for (int jb = 0; jb < 32; jb += 8) {
        float4 r[8];
#pragma unroll
        for (int u = 0; u < 8; ++u)
            r[u] = __ldcs(&nbase[(jb + u) * 32 + lane]);   // MLP=8/warp
#pragma unroll
        for (int u = 0; u < 8; ++u) {
            const float rs = warp_sum((r[u].x + r[u].y) + (r[u].z + r[u].w));
            if (rs != 0.0f) {                              // warp-uniform
                acc.x += r[u].x; acc.y += r[u].y;
                acc.z += r[u].z; acc.w += r[u].w;
                cnt   += 1.0f;
            }
        }
    }
    reinterpret_cast<float4*>(s_acc[w])[lane] = acc;
    if (lane == 0) s_cnt[w] = cnt;

    // concept rows + masks: warps 0..3, one i each
    if (w < 4) {
        const float4 cc = reinterpret_cast<const float4*>(concept_)
                              [(size_t)(bi0 + w) * 32 + lane];
        const float cs = warp_sum((cc.x + cc.y) + (cc.z + cc.w));
        s_cc[w][lane] = cc;
        if (lane == 0) s_mc[w] = (cs != 0.0f) ? 64.0f : 0.0f;
    }
    __syncthreads();

    // ---------------- Phase 2: build packed v' transpose -------------------
    if (tid < 4) s_scale[tid] = s_mc[tid] + s_cnt[2 * tid] + s_cnt[2 * tid + 1];
    {
        const float* s_stu = reinterpret_cast<const float*>(s_stu4);
        const float* s_ccf = reinterpret_cast<const float*>(s_cc);
        float* vT = reinterpret_cast<float*>(s_vT);
#pragma unroll
        for (int pass = 0; pass < 2; ++pass) {
            const int idx = pass * 256 + tid;     // 0..511
            const int i   = idx >> 7;
            const int d   = idx & 127;
            const float mc = s_mc[i];
            const float sc = mc + s_cnt[2 * i] + s_cnt[2 * i + 1];
            const float R  = s_acc[2 * i][d] + s_acc[2 * i + 1][d];
            vT[d * 4 + i]         = fmaf(mc, s_ccf[i * 128 + d], R);  // v
            vT[(128 + d) * 4 + i] = sc * s_stu[d];                    // scale*stu
        }
    }
    __syncthreads();

    // ---------------- Phase 3: 4x128x256 mini-GEMM ------------------------
    // Warp w: k in [32w, 32w+32). Lane owns d-quad d4=lane.
    float4 a0 = make_float4(0.f,0.f,0.f,0.f);
    float4 a1 = a0, a2 = a0, a3 = a0;
    {
        const int kb = w * 32;
        const float4* Wq = reinterpret_cast<const float4*>(W1) + lane;
#pragma unroll 8
        for (int kk = 0; kk < 32; ++kk) {
            const int k = kb + kk;
            const float4 wv = Wq[k * 32];       // W1[k][4*lane..], L1-hot
            const float4 vv = s_vT[k];          // one LDS.128 broadcast
            a0.x = fmaf(vv.x, wv.x, a0.x); a0.y = fmaf(vv.x, wv.y, a0.y);
            a0.z = fmaf(vv.x, wv.z, a0.z); a0.w = fmaf(vv.x, wv.w, a0.w);
            a1.x = fmaf(vv.y, wv.x, a1.x); a1.y = fmaf(vv.y, wv.y, a1.y);
            a1.z = fmaf(vv.y, wv.z, a1.z); a1.w = fmaf(vv.y, wv.w, a1.w);
            a2.x = fmaf(vv.z, wv.x, a2.x); a2.y = fmaf(vv.z, wv.y, a2.y);
            a2.z = fmaf(vv.z, wv.z, a2.z); a2.w = fmaf(vv.z, wv.w, a2.w);
            a3.x = fmaf(vv.w, wv.x, a3.x); a3.y = fmaf(vv.w, wv.y, a3.y);
            a3.z = fmaf(vv.w, wv.z, a3.z); a3.w = fmaf(vv.w, wv.w, a3.w);
        }
    }
    s_part[w][0][lane] = a0;
    s_part[w][1][lane] = a1;
    s_part[w][2][lane] = a2;
    s_part[w][3][lane] = a3;
    __syncthreads();

    // ---------------- Phase 4: reduce partials + epilogue ------------------
    {
        const float* sp = reinterpret_cast<const float*>(s_part); // [8][4][128]
#pragma unroll
        for (int pass = 0; pass < 2; ++pass) {
            const int idx = pass * 256 + tid;
            const int i   = idx >> 7;
            const int d   = idx & 127;
            float o = 0.f;
#pragma unroll
            for (int ww = 0; ww < 8; ++ww)
                o += sp[(ww * 4 + i) * 128 + d];
            out[(size_t)(bi0 + i) * D_ + d] = 0.5f * fmaf(s_scale[i], b1[d], o);
        }
    }
}

extern "C" void kernel_launch(void* const* d_in, const int* in_sizes, int n_in,
                              void* d_out, int out_size)
{
    const float* stu      = (const float*)d_in[0];
    const float* concept_ = (const float*)d_in[1];
    const float* neigh    = (const float*)d_in[2];
    const float* W1       = (const float*)d_in[3];
    const float* b1       = (const float*)d_in[4];
    // d_in[5]=Wn, d_in[6]=bn: dead (softmax over size-1 axis == 1)
    float* out = (float*)d_out;

    neighbor_integration_kernel<<<1024, 256>>>(stu, concept_, neigh, W1, b1, out);
}